// round 3
// baseline (speedup 1.0000x reference)
#include <cuda_runtime.h>

// Problem constants
#define CTC_B 256
#define CTC_T 256
#define CTC_C 512
#define CTC_L 64
#define CHUNK 32
#define NCHUNK (CTC_T / CHUNK)
#define ROWF  66            // smem floats per emission row: 64 labels + blank + pad
#define NEGV  (-1e30f)
#define LOG2E 1.4426950408889634f
#define LN2   0.6931471805599453f
#define NTHREADS 288

__device__ float g_nll[CTC_B];
__device__ unsigned int g_count = 0;

// Named producer/consumer barriers. Total arrivals per instance = NTHREADS
// (256 fill threads + 32 DP threads).
__device__ __forceinline__ void bar_arrive(int id) {
    asm volatile("bar.arrive %0, %1;" :: "r"(id), "r"(NTHREADS) : "memory");
}
__device__ __forceinline__ void bar_sync(int id) {
    asm volatile("bar.sync %0, %1;" :: "r"(id), "r"(NTHREADS) : "memory");
}

__device__ __forceinline__ float warpsum(float v) {
#pragma unroll
    for (int o = 16; o; o >>= 1) v += __shfl_xor_sync(0xffffffffu, v, o);
    return v;
}

// logaddexp in log2 domain
__device__ __forceinline__ float lae2_2(float x, float y) {
    float m = fmaxf(x, y);
    float d = fminf(x, y) - m;
    return m + __log2f(1.0f + exp2f(d));
}
__device__ __forceinline__ float lae2_3(float x, float y, float z) {
    float m = fmaxf(fmaxf(x, y), z);
    float s = exp2f(x - m) + exp2f(y - m) + exp2f(z - m);
    return m + __log2f(s);
}

// One block per batch element, 9 warps.
// Warps 0..7: log-softmax emissions for 32-timestep chunks into a 2-deep smem
// ring. Warp 8: sequential CTC forward DP consuming chunks as they complete.
__global__ void __launch_bounds__(NTHREADS) ctc_fused_kernel(
    const float* __restrict__ logits,
    const int* __restrict__ labels,
    const int* __restrict__ label_length,
    const int* __restrict__ logit_length,
    float* __restrict__ out)
{
    __shared__ float semit[2][CHUNK][ROWF];
    __shared__ int   slab[CTC_L];

    const int b    = blockIdx.x;
    const int tid  = threadIdx.x;
    const int wid  = tid >> 5;
    const int lane = tid & 31;

    if (tid < CTC_L) slab[tid] = labels[b * CTC_L + tid];
    __syncthreads();

    const float* bl = logits + (size_t)b * CTC_T * CTC_C;

    if (wid < 8) {
        // ================= FILL WARPS =================
        const int sy0 = slab[lane];          // label symbols this lane gathers
        const int sy1 = slab[32 + lane];
        const int w4  = wid * (CHUNK / 8);   // 4 rows per warp per chunk

        for (int c = 0; c < NCHUNK; c++) {
            if (c >= 2) bar_sync(3 + (c & 1));   // wait: DP consumed chunk c-2

            const float* rowbase = bl + (size_t)(c * CHUNK + w4) * CTC_C;
            float4 cur[4];
            {
                const float4* rp = (const float4*)rowbase;
#pragma unroll
                for (int k = 0; k < 4; k++) cur[k] = rp[k * 32 + lane];
            }
#pragma unroll
            for (int i = 0; i < CHUNK / 8; i++) {
                float4 nxt[4];
                if (i + 1 < CHUNK / 8) {
                    const float4* np = (const float4*)(rowbase + (size_t)(i + 1) * CTC_C);
#pragma unroll
                    for (int k = 0; k < 4; k++) nxt[k] = np[k * 32 + lane];
                }
                // un-shifted LSE in log2 domain (logits are O(1): no overflow)
                float s = 0.f;
#pragma unroll
                for (int k = 0; k < 4; k++)
                    s += exp2f(cur[k].x * LOG2E) + exp2f(cur[k].y * LOG2E) +
                         exp2f(cur[k].z * LOG2E) + exp2f(cur[k].w * LOG2E);
                s = warpsum(s);
                const float lse2 = __log2f(s);

                const float* rowf = rowbase + (size_t)i * CTC_C;
                float* erow = &semit[c & 1][w4 + i][0];
                erow[lane]      = fmaf(__ldg(rowf + sy0), LOG2E, -lse2);
                erow[32 + lane] = fmaf(__ldg(rowf + sy1), LOG2E, -lse2);
                if (lane == 0)
                    erow[CTC_L] = fmaf(__ldg(rowf + CTC_C - 1), LOG2E, -lse2);
#pragma unroll
                for (int k = 0; k < 4; k++) cur[k] = nxt[k];
            }
            __threadfence_block();
            bar_arrive(1 + (c & 1));             // signal: chunk c ready
        }
    } else {
        // ================= DP WARP =================
        const int tl = logit_length[b];
        const int ll = label_length[b];
        // lane owns states s = 4*lane + j (j=0..3); lane 31 also s=128 (j=4)
        const int  s1    = 4 * lane + 1;
        const bool skip1 = (s1 >= 3) && (slab[2 * lane] != slab[2 * lane - 1]);
        const bool skip3 = (slab[2 * lane + 1] != slab[2 * lane]);

        float a[5], snap[5];
#pragma unroll
        for (int j = 0; j < 5; j++) { a[j] = NEGV; snap[j] = NEGV; }

        for (int c = 0; c < NCHUNK; c++) {
            bar_sync(1 + (c & 1));               // wait: chunk c ready
            const int buf = c & 1;
            int j0 = 0;
            if (c == 0) {
                const float2 eo = *(const float2*)&semit[0][0][2 * lane];
                const float  eb = semit[0][0][CTC_L];
                a[0] = (lane == 0) ? eb   : NEGV;
                a[1] = (lane == 0) ? eo.x : NEGV;
                a[2] = NEGV; a[3] = NEGV; a[4] = NEGV;
                if (tl == 1) {
#pragma unroll
                    for (int q = 0; q < 5; q++) snap[q] = a[q];
                }
                j0 = 1;
            }
#pragma unroll 4
            for (int j = j0; j < CHUNK; j++) {
                const int t = c * CHUNK + j;
                const float2 eo = *(const float2*)&semit[buf][j][2 * lane];
                const float  eb = semit[buf][j][CTC_L];

                float am1 = __shfl_up_sync(0xffffffffu, a[3], 1);  // alpha[4l-1]
                if (lane == 0) am1 = NEGV;
                const float na0 = lae2_2(a[0], am1)                        + eb;
                const float na1 = lae2_3(a[1], a[0], skip1 ? am1  : NEGV)  + eo.x;
                const float na2 = lae2_2(a[2], a[1])                       + eb;
                const float na3 = lae2_3(a[3], a[2], skip3 ? a[1] : NEGV)  + eo.y;
                const float na4 = lae2_2(a[4], a[3])                       + eb;
                a[0] = na0; a[1] = na1; a[2] = na2; a[3] = na3; a[4] = na4;

                if (t == tl - 1) {
#pragma unroll
                    for (int q = 0; q < 5; q++) snap[q] = a[q];
                }
            }
            if (c + 2 < NCHUNK) bar_arrive(3 + (c & 1));  // buffer free
        }

        // -------- finalize --------
        const int se = 2 * ll;          // final blank state
        const int sm = se - 1;
        const float t0 = __shfl_sync(0xffffffffu, snap[0], (se >> 2) & 31);
        const float t1 = __shfl_sync(0xffffffffu, snap[1], (se >> 2) & 31);
        const float t2 = __shfl_sync(0xffffffffu, snap[2], (se >> 2) & 31);
        const float t3 = __shfl_sync(0xffffffffu, snap[3], (se >> 2) & 31);
        const float t4 = __shfl_sync(0xffffffffu, snap[4], 31);
        const float u0 = __shfl_sync(0xffffffffu, snap[0], (sm >> 2) & 31);
        const float u1 = __shfl_sync(0xffffffffu, snap[1], (sm >> 2) & 31);
        const float u2 = __shfl_sync(0xffffffffu, snap[2], (sm >> 2) & 31);
        const float u3 = __shfl_sync(0xffffffffu, snap[3], (sm >> 2) & 31);

        unsigned done = 0;
        if (lane == 0) {
            const int je = se & 3;
            const float v_end = (se >= 128) ? t4
                              : (je == 0 ? t0 : je == 1 ? t1 : je == 2 ? t2 : t3);
            const int jm = sm & 3;
            const float v_m1 = (jm == 0 ? u0 : jm == 1 ? u1 : jm == 2 ? u2 : u3);
            g_nll[b] = -LN2 * lae2_2(v_end, v_m1);
            __threadfence();
            done = (atomicAdd(&g_count, 1u) == CTC_B - 1) ? 1u : 0u;
        }
        done = __shfl_sync(0xffffffffu, done, 0);
        if (done) {
            // deterministic fixed-tree reduction by the last-finishing block
            float s = 0.f;
#pragma unroll
            for (int i = 0; i < CTC_B / 32; i++)
                s += __ldcg(&g_nll[i * 32 + lane]);
            s = warpsum(s);
            if (lane == 0) {
                out[0] = s * (1.0f / CTC_B);
                g_count = 0;                 // reset for next graph replay
            }
        }
    }
}

extern "C" void kernel_launch(void* const* d_in, const int* in_sizes, int n_in,
                              void* d_out, int out_size)
{
    const float* logits       = (const float*)d_in[0];
    const int*   labels       = (const int*)d_in[1];
    const int*   label_length = (const int*)d_in[2];
    const int*   logit_length = (const int*)d_in[3];

    ctc_fused_kernel<<<CTC_B, NTHREADS>>>(logits, labels, label_length,
                                          logit_length, (float*)d_out);
    (void)in_sizes; (void)n_in; (void)out_size;
}